// round 15
// baseline (speedup 1.0000x reference)
#include <cuda_runtime.h>
#include <float.h>
#include <stdint.h>

#define BATCH 8
#define NPT   2048
#define KNB   16
#define BN    (BATCH*NPT)

__device__ float g_D[(size_t)BATCH*NPT*NPT];
__device__ float g_sq[BN];
__device__ float g_sq4[BN*4];
__device__ int   g_idx[BN*KNB];
__device__ float g_x2[BN*32];
__device__ float g_x3[BN*128];
__device__ float g_A [BN*256];
__device__ float g_Bf[BN*256];
__device__ float g_x4[BN*128];
__device__ float g_x5p[BATCH*16*128];
__device__ float g_x7[BATCH*128];
__device__ float g_Xhi[BN*128];
__device__ float g_Xlo[BN*128];
__device__ float g_W2Thi[128*256];   // [n][k], k contiguous
__device__ float g_W2Tlo[128*256];

__device__ __forceinline__ float lrelu(float v) { return v >= 0.f ? v : 0.01f*v; }
__device__ __forceinline__ float tf32r(float x) {
    uint32_t u; asm("cvt.rna.tf32.f32 %0, %1;" : "=r"(u) : "f"(x));
    return __uint_as_float(u);
}
__device__ __forceinline__ uint32_t smem_u32(const void* p) {
    uint32_t a;
    asm("{ .reg .u64 t; cvta.to.shared.u64 t, %1; cvt.u32.u64 %0, t; }" : "=r"(a) : "l"(p));
    return a;
}
__device__ __forceinline__ void cpa16(uint32_t saddr, const void* g) {
    asm volatile("cp.async.cg.shared.global [%0], [%1], 16;" :: "r"(saddr), "l"(g));
}
#define CPA_COMMIT() asm volatile("cp.async.commit_group;" ::: "memory")
#define CPA_WAIT0()  asm volatile("cp.async.wait_group 0;" ::: "memory")

__device__ __forceinline__ void mma8(float c[4], const uint32_t a[4], const uint32_t b[2]) {
    asm("mma.sync.aligned.m16n8k8.row.col.f32.tf32.tf32.f32 "
        "{%0,%1,%2,%3}, {%4,%5,%6,%7}, {%8,%9}, {%0,%1,%2,%3};"
        : "+f"(c[0]), "+f"(c[1]), "+f"(c[2]), "+f"(c[3])
        : "r"(a[0]), "r"(a[1]), "r"(a[2]), "r"(a[3]), "r"(b[0]), "r"(b[1]));
}

// XOR-swizzled index within a 128-row x 32-float K-major tile (conflict-free)
__device__ __forceinline__ int swidx(int row, int kq) {
    return row*32 + (kq ^ ((row & 7) << 2));
}

// warp GEMM over one K=32 chunk: 3-pass tf32 split, warp tile 32x32
// A: hi at +0, lo at +4096 ; B likewise
__device__ __forceinline__ void chunk_gemm(const float* __restrict__ A,
                                           const float* __restrict__ B,
                                           float (&c)[2][4][4],
                                           int rb, int cb, int g, int tq) {
    #pragma unroll
    for (int ks = 0; ks < 4; ks++) {
        int k0 = ks*8;
        uint32_t aH[2][4], aL[2][4], bH[4][2], bL[4][2];
        #pragma unroll
        for (int mt = 0; mt < 2; mt++) {
            int r0 = rb + mt*16 + g;
            int i00 = swidx(r0,   k0+tq), i01 = swidx(r0,   k0+tq+4);
            int i10 = swidx(r0+8, k0+tq), i11 = swidx(r0+8, k0+tq+4);
            aH[mt][0]=__float_as_uint(A[i00]); aH[mt][1]=__float_as_uint(A[i10]);
            aH[mt][2]=__float_as_uint(A[i01]); aH[mt][3]=__float_as_uint(A[i11]);
            aL[mt][0]=__float_as_uint(A[4096+i00]); aL[mt][1]=__float_as_uint(A[4096+i10]);
            aL[mt][2]=__float_as_uint(A[4096+i01]); aL[mt][3]=__float_as_uint(A[4096+i11]);
        }
        #pragma unroll
        for (int nt = 0; nt < 4; nt++) {
            int n0 = cb + nt*8 + g;
            int j0i = swidx(n0, k0+tq), j1i = swidx(n0, k0+tq+4);
            bH[nt][0]=__float_as_uint(B[j0i]); bH[nt][1]=__float_as_uint(B[j1i]);
            bL[nt][0]=__float_as_uint(B[4096+j0i]); bL[nt][1]=__float_as_uint(B[4096+j1i]);
        }
        #pragma unroll
        for (int mt = 0; mt < 2; mt++)
            #pragma unroll
            for (int nt = 0; nt < 4; nt++) {
                mma8(c[mt][nt], aH[mt], bH[nt]);
                mma8(c[mt][nt], aL[mt], bH[nt]);
                mma8(c[mt][nt], aH[mt], bL[nt]);
            }
    }
}

__global__ __launch_bounds__(256) void prepw2_kernel(const float* __restrict__ W2) {
    int e = blockIdx.x*256 + threadIdx.x;   // 32768 = 256x128
    if (e >= 32768) return;
    int k = e >> 7, n = e & 127;
    float x = W2[e];
    float hi = tf32r(x);
    g_W2Thi[n*256 + k] = hi;
    g_W2Tlo[n*256 + k] = tf32r(x - hi);
}

// ======== dist C=3 (FFMA, norms inline) ========
__global__ __launch_bounds__(256) void dist3_kernel(const float* __restrict__ X) {
    __shared__ float As[3][65], Bs[3][65];
    int b = blockIdx.z, i0 = blockIdx.y*64, j0 = blockIdx.x*64;
    const float* Xb = X + (size_t)b*NPT*3;
    int t = threadIdx.x, tx = t & 15, ty = t >> 4;
    for (int e = t; e < 192; e += 256) {
        int r = e/3, c = e%3;
        As[c][r] = Xb[(size_t)(i0+r)*3 + c];
        Bs[c][r] = Xb[(size_t)(j0+r)*3 + c];
    }
    __syncthreads();
    float acc[4][4] = {};
    #pragma unroll
    for (int c = 0; c < 3; c++) {
        float av[4], bv[4];
        #pragma unroll
        for (int u = 0; u < 4; u++) { av[u] = As[c][ty*4+u]; bv[u] = Bs[c][tx*4+u]; }
        #pragma unroll
        for (int i = 0; i < 4; i++)
            #pragma unroll
            for (int j = 0; j < 4; j++) acc[i][j] += av[i]*bv[j];
    }
    float sj[4], si[4];
    #pragma unroll
    for (int u = 0; u < 4; u++) {
        int jr = tx*4 + u, ir = ty*4 + u;
        sj[u] = Bs[0][jr]*Bs[0][jr] + Bs[1][jr]*Bs[1][jr] + Bs[2][jr]*Bs[2][jr];
        si[u] = As[0][ir]*As[0][ir] + As[1][ir]*As[1][ir] + As[2][ir]*As[2][ir];
    }
    float* Db = g_D + (size_t)b*NPT*NPT;
    int j = j0 + tx*4;
    #pragma unroll
    for (int i = 0; i < 4; i++) {
        int ii = i0 + ty*4 + i;
        float4 o = { si[i]+sj[0]-2.f*acc[i][0], si[i]+sj[1]-2.f*acc[i][1],
                     si[i]+sj[2]-2.f*acc[i][2], si[i]+sj[3]-2.f*acc[i][3] };
        *(float4*)(Db + (size_t)ii*NPT + j) = o;
    }
}

// ======== dist via mma.sync, triangular grid, single-buffer, 3 CTA/SM ========
#define DIST_SM (17152*4)
template<int C, bool SQ4>
__global__ __launch_bounds__(512) void dist_mma() {
    extern __shared__ __align__(16) float sm[];
    float* sqi = sm + 16896; float* sqj = sm + 17024;
    int t = threadIdx.x, wid = t >> 5, lane = t & 31;
    int g = lane >> 2, tq = lane & 3;
    int rb = (wid & 3)*32, cb = (wid >> 2)*32;
    int b = blockIdx.z;
    int L = blockIdx.x, bi = 0;
    while (L >= 16 - bi) { L -= 16 - bi; bi++; }
    int bj = bi + L;
    int i0 = bi*128, j0 = bj*128;
    if (t < 128) {
        if (SQ4) {
            float4 a = *(const float4*)(g_sq4 + (size_t)(b*NPT + i0 + t)*4);
            float4 c4 = *(const float4*)(g_sq4 + (size_t)(b*NPT + j0 + t)*4);
            sqi[t] = (a.x + a.y) + (a.z + a.w);
            sqj[t] = (c4.x + c4.y) + (c4.z + c4.w);
        } else {
            sqi[t] = g_sq[b*NPT + i0 + t];
            sqj[t] = g_sq[b*NPT + j0 + t];
        }
    }
    const float* XiH = g_Xhi + (size_t)(b*NPT + i0)*C;
    const float* XiL = g_Xlo + (size_t)(b*NPT + i0)*C;
    const float* XjH = g_Xhi + (size_t)(b*NPT + j0)*C;
    const float* XjL = g_Xlo + (size_t)(b*NPT + j0)*C;
    uint32_t smb = smem_u32(sm);
    constexpr int NC = C/32;
    float c[2][4][4] = {};
    #pragma unroll 1
    for (int ch = 0; ch < NC; ch++) {
        __syncthreads();
        for (int e = t; e < 4096; e += 512) {
            int arr = e >> 10, le = e & 1023, row = le >> 3, q = le & 7;
            const float* src = (arr == 0) ? XiH : (arr == 1) ? XiL : (arr == 2) ? XjH : XjL;
            uint32_t dst = smb + (uint32_t)(arr*4096 + row*32 + 4*(q ^ (row & 7)))*4u;
            cpa16(dst, src + (size_t)row*C + ch*32 + q*4);
        }
        CPA_COMMIT(); CPA_WAIT0();
        __syncthreads();
        chunk_gemm(sm, sm + 8192, c, rb, cb, g, tq);
    }
    __syncthreads();
    float* stage = sm;
    #pragma unroll
    for (int mt = 0; mt < 2; mt++) {
        int r0 = rb + mt*16 + g;
        float si0 = sqi[r0], si1 = sqi[r0 + 8];
        #pragma unroll
        for (int nt = 0; nt < 4; nt++) {
            int cl = cb + nt*8 + 2*tq;
            float sj0 = sqj[cl], sj1 = sqj[cl + 1];
            stage[r0*132 + cl]     = si0 + sj0 - 2.f*c[mt][nt][0];
            stage[r0*132 + cl + 1] = si0 + sj1 - 2.f*c[mt][nt][1];
            stage[(r0+8)*132 + cl]     = si1 + sj0 - 2.f*c[mt][nt][2];
            stage[(r0+8)*132 + cl + 1] = si1 + sj1 - 2.f*c[mt][nt][3];
        }
    }
    __syncthreads();
    float* Db = g_D + (size_t)b*NPT*NPT;
    for (int e = t; e < 4096; e += 512) {
        int r = e >> 5, q = e & 31;
        float4 v = *(const float4*)(stage + r*132 + q*4);
        *(float4*)(Db + (size_t)(i0 + r)*NPT + j0 + q*4) = v;
    }
    if (bi != bj) {
        __syncthreads();
        #pragma unroll
        for (int mt = 0; mt < 2; mt++) {
            int r0 = rb + mt*16 + g;
            float si0 = sqi[r0], si1 = sqi[r0 + 8];
            #pragma unroll
            for (int nt = 0; nt < 4; nt++) {
                int cl = cb + nt*8 + 2*tq;
                float sj0 = sqj[cl], sj1 = sqj[cl + 1];
                stage[cl*132 + r0]     = si0 + sj0 - 2.f*c[mt][nt][0];
                stage[(cl+1)*132 + r0] = si0 + sj1 - 2.f*c[mt][nt][1];
                stage[cl*132 + r0 + 8]     = si1 + sj0 - 2.f*c[mt][nt][2];
                stage[(cl+1)*132 + r0 + 8] = si1 + sj1 - 2.f*c[mt][nt][3];
            }
        }
        __syncthreads();
        for (int e = t; e < 4096; e += 512) {
            int r = e >> 5, q = e & 31;
            float4 v = *(const float4*)(stage + r*132 + q*4);
            *(float4*)(Db + (size_t)(j0 + r)*NPT + i0 + q*4) = v;
        }
    }
}

// ======== top-16: register-resident candidates ========
__global__ __launch_bounds__(256) void topk_kernel() {
    __shared__ float rbest[8]; __shared__ int ribest[8]; __shared__ int winner;
    int row = blockIdx.x, t = threadIdx.x;
    const float* Dr = g_D + (size_t)row * NPT;
    float v[8];
    #pragma unroll
    for (int u = 0; u < 8; u++) v[u] = Dr[t + u*256];
    #pragma unroll 1
    for (int it = 0; it < KNB; it++) {
        float best = v[0]; int bu = 0;
        #pragma unroll
        for (int u = 1; u < 8; u++) if (v[u] < best) { best = v[u]; bu = u; }
        int bi = t + bu*256;
        #pragma unroll
        for (int o = 16; o; o >>= 1) {
            float ov = __shfl_down_sync(0xffffffffu, best, o);
            int   oi = __shfl_down_sync(0xffffffffu, bi, o);
            if (ov < best || (ov == best && oi < bi)) { best = ov; bi = oi; }
        }
        if ((t & 31) == 0) { rbest[t>>5] = best; ribest[t>>5] = bi; }
        __syncthreads();
        if (t == 0) {
            #pragma unroll
            for (int w = 1; w < 8; w++)
                if (rbest[w] < best || (rbest[w] == best && ribest[w] < bi)) { best = rbest[w]; bi = ribest[w]; }
            g_idx[row*KNB + it] = bi;
            winner = bi;
        }
        __syncthreads();
        int wbi = winner;
        if ((wbi & 255) == t) {
            int uu = wbi >> 8;
            #pragma unroll
            for (int u = 0; u < 8; u++) if (u == uu) v[u] = FLT_MAX;
        }
    }
}

// ======== block 1 edge MLP + fused sq/split for stage 2 ========
__global__ __launch_bounds__(128) void mlp1_kernel(
        const float* __restrict__ x,
        const float* __restrict__ w1, const float* __restrict__ b1,
        const float* __restrict__ w2, const float* __restrict__ b2,
        const float* __restrict__ w3, const float* __restrict__ b3) {
    __shared__ float s1[96], sb1[16], s2[1024], sb2[64], s3[2048], sb3[32];
    int t = threadIdx.x;
    if (t < 96) s1[t] = w1[t];
    if (t < 16) sb1[t] = b1[t];
    for (int e = t; e < 1024; e += 128) s2[e] = w2[e];
    if (t < 64) sb2[t] = b2[t];
    for (int e = t; e < 2048; e += 128) s3[e] = w3[e];
    if (t < 32) sb3[t] = b3[t];
    __syncthreads();
    int k = t & 15, lp = t >> 4;
    int p = blockIdx.x * 8 + lp, b = p >> 11;
    int j = g_idx[p*KNB + k];
    const float* xc = x + (size_t)p*3;
    const float* xn = x + (size_t)(b*NPT + j)*3;
    float in[6] = { xc[0], xc[1], xc[2], xn[0], xn[1], xn[2] };
    float h16[16];
    #pragma unroll
    for (int o4 = 0; o4 < 4; o4++) {
        float4 a = *(const float4*)(sb1 + o4*4);
        #pragma unroll
        for (int c = 0; c < 6; c++) {
            float4 w = *(const float4*)(s1 + c*16 + o4*4);
            float v = in[c];
            a.x += w.x*v; a.y += w.y*v; a.z += w.z*v; a.w += w.w*v;
        }
        h16[o4*4+0] = lrelu(a.x); h16[o4*4+1] = lrelu(a.y);
        h16[o4*4+2] = lrelu(a.z); h16[o4*4+3] = lrelu(a.w);
    }
    float h32[32];
    #pragma unroll
    for (int o = 0; o < 32; o++) h32[o] = sb3[o];
    #pragma unroll
    for (int oc = 0; oc < 4; oc++) {
        float t16[16];
        #pragma unroll
        for (int o4 = 0; o4 < 4; o4++) {
            float4 a = *(const float4*)(sb2 + oc*16 + o4*4);
            #pragma unroll
            for (int c = 0; c < 16; c++) {
                float4 w = *(const float4*)(s2 + c*64 + oc*16 + o4*4);
                float v = h16[c];
                a.x += w.x*v; a.y += w.y*v; a.z += w.z*v; a.w += w.w*v;
            }
            t16[o4*4+0] = lrelu(a.x); t16[o4*4+1] = lrelu(a.y);
            t16[o4*4+2] = lrelu(a.z); t16[o4*4+3] = lrelu(a.w);
        }
        #pragma unroll
        for (int cc = 0; cc < 16; cc++) {
            float v = t16[cc];
            int c = oc*16 + cc;
            #pragma unroll
            for (int o4 = 0; o4 < 8; o4++) {
                float4 w = *(const float4*)(s3 + c*32 + o4*4);
                h32[o4*4+0] += w.x*v; h32[o4*4+1] += w.y*v;
                h32[o4*4+2] += w.z*v; h32[o4*4+3] += w.w*v;
            }
        }
    }
    #pragma unroll
    for (int c = 0; c < 32; c++) {
        float v = lrelu(h32[c]);
        #pragma unroll
        for (int o = 8; o; o >>= 1) v += __shfl_xor_sync(0xffffffffu, v, o);
        h32[c] = v;
    }
    if (k == 0) {
        float* outp = g_x2 + (size_t)p*32;
        float* hip  = g_Xhi + (size_t)p*32;
        float* lop  = g_Xlo + (size_t)p*32;
        float sq = 0.f;
        #pragma unroll
        for (int c = 0; c < 32; c++) {
            float v = h32[c];
            outp[c] = v;
            sq += v*v;
            float hi = tf32r(v);
            hip[c] = hi;
            lop[c] = tf32r(v - hi);
        }
        g_sq[p] = sq;
    }
}

// ======== factored layer-1 projections ========
template<int CIN, int COUT>
__global__ __launch_bounds__(256) void proj_kernel(
        const float* __restrict__ X, const float* __restrict__ W,
        const float* __restrict__ bias) {
    constexpr int OG = COUT/4;
    constexpr int R  = 256/OG;
    __shared__ float sin[R][CIN];
    int t = threadIdx.x, p0 = blockIdx.x * R;
    for (int e = t; e < R*CIN; e += 256) sin[e/CIN][e%CIN] = X[(size_t)p0*CIN + e];
    __syncthreads();
    int og = t % OG, r = t / OG;
    float4 aa = {0,0,0,0}, bb = {0,0,0,0};
    #pragma unroll 4
    for (int c = 0; c < CIN; c++) {
        float v = sin[r][c];
        float4 wa = *(const float4*)(W + (size_t)c*COUT + og*4);
        float4 wb = *(const float4*)(W + (size_t)(CIN+c)*COUT + og*4);
        aa.x += wa.x*v; aa.y += wa.y*v; aa.z += wa.z*v; aa.w += wa.w*v;
        bb.x += wb.x*v; bb.y += wb.y*v; bb.z += wb.z*v; bb.w += wb.w*v;
    }
    float4 b4 = *(const float4*)(bias + og*4);
    aa.x += b4.x; aa.y += b4.y; aa.z += b4.z; aa.w += b4.w;
    *(float4*)(g_A  + (size_t)(p0+r)*COUT + og*4) = aa;
    *(float4*)(g_Bf + (size_t)(p0+r)*COUT + og*4) = bb;
}

// ======== block 2 layer-2 via mma.sync + fused sq/split for stage 3 ========
#define MLP2_SM (17152*4)
__global__ __launch_bounds__(512) void mlp2_mma(const float* __restrict__ b2) {
    extern __shared__ __align__(16) float sm[];
    float* Hhi = sm;
    float* b2s = sm + 16896;
    int*   rowsrc = (int*)(sm + 17024);
    int t = threadIdx.x, wid = t >> 5, lane = t & 31;
    int g = lane >> 2, tq = lane & 3;
    int rb = (wid & 3)*32, cb = (wid >> 2)*32;
    int p0 = blockIdx.x*8, b = p0 >> 11;
    uint32_t smb = smem_u32(sm);
    if (t < 128) {
        b2s[t] = b2[t];
        rowsrc[t] = b*NPT + g_idx[(p0 + (t>>4))*KNB + (t & 15)];
    }
    __syncthreads();
    float c[2][4][4] = {};
    #pragma unroll 1
    for (int ch = 0; ch < 8; ch++) {
        for (int e = t; e < 2048; e += 512) {
            int arr = e >> 10, le = e & 1023, n = le >> 3, q = le & 7;
            const float* src = arr ? g_W2Tlo : g_W2Thi;
            uint32_t dst = smb + (uint32_t)(8192 + arr*4096 + n*32 + 4*(q ^ (n & 7)))*4u;
            cpa16(dst, src + (size_t)n*256 + ch*32 + q*4);
        }
        CPA_COMMIT();
        for (int e = t; e < 4096; e += 512) {
            int row = e >> 5, kq = e & 31, ci = ch*32 + kq;
            float v = lrelu(g_A[(size_t)(p0 + (row>>4))*256 + ci] + g_Bf[(size_t)rowsrc[row]*256 + ci]);
            float hi = tf32r(v);
            int si = swidx(row, kq);
            Hhi[si] = hi;
            Hhi[4096 + si] = tf32r(v - hi);
        }
        CPA_WAIT0();
        __syncthreads();
        chunk_gemm(Hhi, sm + 8192, c, rb, cb, g, tq);
        __syncthreads();
    }
    float* stage = sm;
    #pragma unroll
    for (int mt = 0; mt < 2; mt++) {
        int r0 = rb + mt*16 + g;
        #pragma unroll
        for (int nt = 0; nt < 4; nt++) {
            int cl = cb + nt*8 + 2*tq;
            float bb0 = b2s[cl], bb1 = b2s[cl + 1];
            stage[r0*132 + cl]     = lrelu(c[mt][nt][0] + bb0);
            stage[r0*132 + cl + 1] = lrelu(c[mt][nt][1] + bb1);
            stage[(r0+8)*132 + cl]     = lrelu(c[mt][nt][2] + bb0);
            stage[(r0+8)*132 + cl + 1] = lrelu(c[mt][nt][3] + bb1);
        }
    }
    __syncthreads();
    for (int o = t; o < 1024; o += 512) {
        int pl = o >> 7, cl = o & 127;
        const float* sp = stage + (pl*16)*132 + cl;
        float s = 0.f;
        #pragma unroll
        for (int kk = 0; kk < 16; kk++) s += sp[kk*132];
        size_t gi = (size_t)(p0 + pl)*128 + cl;
        g_x3[gi] = s;
        float hi = tf32r(s);
        g_Xhi[gi] = hi;
        g_Xlo[gi] = tf32r(s - hi);
        // per-warp partial sum of s^2 (pl constant within warp; 32 cols per warp)
        float ss = s*s;
        #pragma unroll
        for (int sh = 16; sh; sh >>= 1) ss += __shfl_xor_sync(0xffffffffu, ss, sh);
        if ((t & 31) == 0) g_sq4[(size_t)(p0 + pl)*4 + ((t >> 5) & 3)] = ss;
    }
}

// ======== block 3 (fully factored) ========
__global__ __launch_bounds__(128) void block3_kernel() {
    __shared__ int idxs[KNB];
    int p = blockIdx.x, t = threadIdx.x, b = p >> 11;
    if (t < KNB) idxs[t] = g_idx[p*KNB + t];
    __syncthreads();
    float a = g_A[(size_t)p*128 + t];
    float acc = 0.f;
    #pragma unroll
    for (int k = 0; k < KNB; k++)
        acc += lrelu(a + g_Bf[(size_t)(b*NPT + idxs[k])*128 + t]);
    g_x4[(size_t)p*128 + t] = acc;
}

// ======== max pool + head ========
__global__ __launch_bounds__(128) void maxpool_kernel() {
    int b = blockIdx.x, seg = blockIdx.y, t = threadIdx.x;
    const float* base = g_x4 + ((size_t)b*NPT + seg*128)*128 + t;
    float m = -FLT_MAX;
    #pragma unroll 8
    for (int r = 0; r < 128; r++) m = fmaxf(m, base[(size_t)r*128]);
    g_x5p[(b*16 + seg)*128 + t] = m;
}

__global__ __launch_bounds__(128) void final12_kernel(
        const float* __restrict__ fc1w, const float* __restrict__ fc1b,
        const float* __restrict__ fc2w, const float* __restrict__ fc2b) {
    __shared__ float s5[128], s6[128];
    int b = blockIdx.x, t = threadIdx.x;
    float m = -FLT_MAX;
    #pragma unroll
    for (int s = 0; s < 16; s++) m = fmaxf(m, g_x5p[(b*16+s)*128 + t]);
    s5[t] = m;
    __syncthreads();
    float a = fc1b[t];
    #pragma unroll 8
    for (int c = 0; c < 128; c++) a += fc1w[c*128+t]*s5[c];
    s6[t] = lrelu(a);
    __syncthreads();
    a = fc2b[t];
    #pragma unroll 8
    for (int c = 0; c < 128; c++) a += fc2w[c*128+t]*s6[c];
    g_x7[b*128 + t] = lrelu(a);
}

__global__ __launch_bounds__(128) void fc3_kernel(
        const float* __restrict__ fc3w, const float* __restrict__ fc3b,
        float* __restrict__ out) {
    __shared__ float s7[128];
    int b = blockIdx.x, seg = blockIdx.y, t = threadIdx.x;
    s7[t] = g_x7[b*128 + t];
    __syncthreads();
    int o0 = seg*512;
    float acc[4];
    #pragma unroll
    for (int u = 0; u < 4; u++) acc[u] = fc3b[o0 + u*128 + t];
    #pragma unroll 4
    for (int c = 0; c < 128; c++) {
        float v = s7[c];
        const float* wr = fc3w + (size_t)c*6144 + o0 + t;
        #pragma unroll
        for (int u = 0; u < 4; u++) acc[u] += wr[u*128]*v;
    }
    float* ob = out + (size_t)b*6144 + o0;
    #pragma unroll
    for (int u = 0; u < 4; u++) ob[u*128 + t] = acc[u];
}

// ======== host ========
extern "C" void kernel_launch(void* const* d_in, const int* in_sizes, int n_in,
                              void* d_out, int out_size) {
    const float* x    = (const float*)d_in[0];
    const float* h1w1 = (const float*)d_in[1];
    const float* h1b1 = (const float*)d_in[2];
    const float* h1w2 = (const float*)d_in[3];
    const float* h1b2 = (const float*)d_in[4];
    const float* h1w3 = (const float*)d_in[5];
    const float* h1b3 = (const float*)d_in[6];
    const float* h2w1 = (const float*)d_in[7];
    const float* h2b1 = (const float*)d_in[8];
    const float* h2w2 = (const float*)d_in[9];
    const float* h2b2 = (const float*)d_in[10];
    const float* h3w1 = (const float*)d_in[11];
    const float* h3b1 = (const float*)d_in[12];
    const float* fc1w = (const float*)d_in[13];
    const float* fc1b = (const float*)d_in[14];
    const float* fc2w = (const float*)d_in[15];
    const float* fc2b = (const float*)d_in[16];
    const float* fc3w = (const float*)d_in[17];
    const float* fc3b = (const float*)d_in[18];
    float* out = (float*)d_out;

    cudaFuncSetAttribute((const void*)dist_mma<32,false>,  cudaFuncAttributeMaxDynamicSharedMemorySize, DIST_SM);
    cudaFuncSetAttribute((const void*)dist_mma<128,true>,  cudaFuncAttributeMaxDynamicSharedMemorySize, DIST_SM);
    cudaFuncSetAttribute((const void*)mlp2_mma,            cudaFuncAttributeMaxDynamicSharedMemorySize, MLP2_SM);

    void* p2; cudaGetSymbolAddress(&p2, g_x2);
    void* p3; cudaGetSymbolAddress(&p3, g_x3);
    dim3 d3grid(32, 32, BATCH);
    dim3 trigrid(136, 1, BATCH);

    // stage 1 (C=3)
    dist3_kernel<<<d3grid, 256>>>(x);                                        // 1
    topk_kernel<<<BN, 256>>>();                                              // 2
    mlp1_kernel<<<BN/8, 128>>>(x, h1w1, h1b1, h1w2, h1b2, h1w3, h1b3);       // 3 (writes x2 + split + sq)

    // stage 2 (C=32)
    dist_mma<32,false><<<trigrid, 512, DIST_SM>>>();                         // 4 <- ncu target
    topk_kernel<<<BN, 256>>>();                                              // 5
    proj_kernel<32, 256><<<BN/4, 256>>>((const float*)p2, h2w1, h2b1);       // 6
    prepw2_kernel<<<128, 256>>>(h2w2);                                       // 7
    mlp2_mma<<<BN/8, 512, MLP2_SM>>>(h2b2);                                  // 8 (writes x3 + split + sq4)

    // stage 3 (C=128)
    dist_mma<128,true><<<trigrid, 512, DIST_SM>>>();                         // 9
    topk_kernel<<<BN, 256>>>();                                              // 10
    proj_kernel<128, 128><<<BN/8, 256>>>((const float*)p3, h3w1, h3b1);      // 11
    block3_kernel<<<BN, 128>>>();                                            // 12

    // head
    maxpool_kernel<<<dim3(BATCH, 16), 128>>>();                              // 13
    final12_kernel<<<BATCH, 128>>>(fc1w, fc1b, fc2w, fc2b);                  // 14
    fc3_kernel<<<dim3(BATCH, 12), 128>>>(fc3w, fc3b, out);                   // 15
}

// round 16
// speedup vs baseline: 1.1233x; 1.1233x over previous
#include <cuda_runtime.h>
#include <float.h>
#include <stdint.h>

#define BATCH 8
#define NPT   2048
#define KNB   16
#define BN    (BATCH*NPT)

__device__ float g_D[(size_t)BATCH*NPT*NPT];
__device__ float g_sq[BN];
__device__ float g_sq4[BN*4];
__device__ int   g_idx[BN*KNB];
__device__ float g_x2[BN*32];
__device__ float g_x3[BN*128];
__device__ float g_A [BN*256];
__device__ float g_Bf[BN*256];
__device__ float g_x4[BN*128];
__device__ float g_x5p[BATCH*16*128];
__device__ float g_x7[BATCH*128];
__device__ float g_Xhi[BN*128];
__device__ float g_Xlo[BN*128];
__device__ float g_W2Thi[128*256];   // [n][k], k contiguous
__device__ float g_W2Tlo[128*256];

__device__ __forceinline__ float lrelu(float v) { return v >= 0.f ? v : 0.01f*v; }
__device__ __forceinline__ float tf32r(float x) {
    uint32_t u; asm("cvt.rna.tf32.f32 %0, %1;" : "=r"(u) : "f"(x));
    return __uint_as_float(u);
}
__device__ __forceinline__ uint32_t smem_u32(const void* p) {
    uint32_t a;
    asm("{ .reg .u64 t; cvta.to.shared.u64 t, %1; cvt.u32.u64 %0, t; }" : "=r"(a) : "l"(p));
    return a;
}
__device__ __forceinline__ void cpa16(uint32_t saddr, const void* g) {
    asm volatile("cp.async.cg.shared.global [%0], [%1], 16;" :: "r"(saddr), "l"(g));
}
#define CPA_COMMIT() asm volatile("cp.async.commit_group;" ::: "memory")
#define CPA_WAIT0()  asm volatile("cp.async.wait_group 0;" ::: "memory")

__device__ __forceinline__ void mma8(float c[4], const uint32_t a[4], const uint32_t b[2]) {
    asm("mma.sync.aligned.m16n8k8.row.col.f32.tf32.tf32.f32 "
        "{%0,%1,%2,%3}, {%4,%5,%6,%7}, {%8,%9}, {%0,%1,%2,%3};"
        : "+f"(c[0]), "+f"(c[1]), "+f"(c[2]), "+f"(c[3])
        : "r"(a[0]), "r"(a[1]), "r"(a[2]), "r"(a[3]), "r"(b[0]), "r"(b[1]));
}

// XOR-swizzled index within a 128-row x 32-float K-major tile (conflict-free)
__device__ __forceinline__ int swidx(int row, int kq) {
    return row*32 + (kq ^ ((row & 7) << 2));
}

// warp GEMM over one K=32 chunk: 3-pass tf32 split, warp tile 32x32.
// Operand fragments loaded inside mt/nt loops to keep live regs ~56 (2 CTA/SM).
__device__ __forceinline__ void chunk_gemm(const float* __restrict__ A,
                                           const float* __restrict__ B,
                                           float (&c)[2][4][4],
                                           int rb, int cb, int g, int tq) {
    #pragma unroll
    for (int ks = 0; ks < 4; ks++) {
        int k0 = ks*8;
        #pragma unroll
        for (int mt = 0; mt < 2; mt++) {
            int r0 = rb + mt*16 + g;
            int i00 = swidx(r0,   k0+tq), i01 = swidx(r0,   k0+tq+4);
            int i10 = swidx(r0+8, k0+tq), i11 = swidx(r0+8, k0+tq+4);
            uint32_t aH[4], aL[4];
            aH[0]=__float_as_uint(A[i00]); aH[1]=__float_as_uint(A[i10]);
            aH[2]=__float_as_uint(A[i01]); aH[3]=__float_as_uint(A[i11]);
            aL[0]=__float_as_uint(A[4096+i00]); aL[1]=__float_as_uint(A[4096+i10]);
            aL[2]=__float_as_uint(A[4096+i01]); aL[3]=__float_as_uint(A[4096+i11]);
            #pragma unroll
            for (int nt = 0; nt < 4; nt++) {
                int n0 = cb + nt*8 + g;
                int j0i = swidx(n0, k0+tq), j1i = swidx(n0, k0+tq+4);
                uint32_t bH[2], bL[2];
                bH[0]=__float_as_uint(B[j0i]); bH[1]=__float_as_uint(B[j1i]);
                bL[0]=__float_as_uint(B[4096+j0i]); bL[1]=__float_as_uint(B[4096+j1i]);
                mma8(c[mt][nt], aH, bH);
                mma8(c[mt][nt], aL, bH);
                mma8(c[mt][nt], aH, bL);
            }
        }
    }
}

__global__ __launch_bounds__(256) void prepw2_kernel(const float* __restrict__ W2) {
    int e = blockIdx.x*256 + threadIdx.x;   // 32768 = 256x128
    if (e >= 32768) return;
    int k = e >> 7, n = e & 127;
    float x = W2[e];
    float hi = tf32r(x);
    g_W2Thi[n*256 + k] = hi;
    g_W2Tlo[n*256 + k] = tf32r(x - hi);
}

// ======== dist C=3 (FFMA, norms inline) ========
__global__ __launch_bounds__(256) void dist3_kernel(const float* __restrict__ X) {
    __shared__ float As[3][65], Bs[3][65];
    int b = blockIdx.z, i0 = blockIdx.y*64, j0 = blockIdx.x*64;
    const float* Xb = X + (size_t)b*NPT*3;
    int t = threadIdx.x, tx = t & 15, ty = t >> 4;
    for (int e = t; e < 192; e += 256) {
        int r = e/3, c = e%3;
        As[c][r] = Xb[(size_t)(i0+r)*3 + c];
        Bs[c][r] = Xb[(size_t)(j0+r)*3 + c];
    }
    __syncthreads();
    float acc[4][4] = {};
    #pragma unroll
    for (int c = 0; c < 3; c++) {
        float av[4], bv[4];
        #pragma unroll
        for (int u = 0; u < 4; u++) { av[u] = As[c][ty*4+u]; bv[u] = Bs[c][tx*4+u]; }
        #pragma unroll
        for (int i = 0; i < 4; i++)
            #pragma unroll
            for (int j = 0; j < 4; j++) acc[i][j] += av[i]*bv[j];
    }
    float sj[4], si[4];
    #pragma unroll
    for (int u = 0; u < 4; u++) {
        int jr = tx*4 + u, ir = ty*4 + u;
        sj[u] = Bs[0][jr]*Bs[0][jr] + Bs[1][jr]*Bs[1][jr] + Bs[2][jr]*Bs[2][jr];
        si[u] = As[0][ir]*As[0][ir] + As[1][ir]*As[1][ir] + As[2][ir]*As[2][ir];
    }
    float* Db = g_D + (size_t)b*NPT*NPT;
    int j = j0 + tx*4;
    #pragma unroll
    for (int i = 0; i < 4; i++) {
        int ii = i0 + ty*4 + i;
        float4 o = { si[i]+sj[0]-2.f*acc[i][0], si[i]+sj[1]-2.f*acc[i][1],
                     si[i]+sj[2]-2.f*acc[i][2], si[i]+sj[3]-2.f*acc[i][3] };
        *(float4*)(Db + (size_t)ii*NPT + j) = o;
    }
}

// ======== dist via mma.sync, triangular grid, 2 CTA/SM ========
#define DIST_SM (17152*4)
template<int C, bool SQ4>
__global__ __launch_bounds__(512, 2) void dist_mma() {
    extern __shared__ __align__(16) float sm[];
    float* sqi = sm + 16896; float* sqj = sm + 17024;
    int t = threadIdx.x, wid = t >> 5, lane = t & 31;
    int g = lane >> 2, tq = lane & 3;
    int rb = (wid & 3)*32, cb = (wid >> 2)*32;
    int b = blockIdx.z;
    int L = blockIdx.x, bi = 0;
    while (L >= 16 - bi) { L -= 16 - bi; bi++; }
    int bj = bi + L;
    int i0 = bi*128, j0 = bj*128;
    if (t < 128) {
        if (SQ4) {
            float4 a = *(const float4*)(g_sq4 + (size_t)(b*NPT + i0 + t)*4);
            float4 c4 = *(const float4*)(g_sq4 + (size_t)(b*NPT + j0 + t)*4);
            sqi[t] = (a.x + a.y) + (a.z + a.w);
            sqj[t] = (c4.x + c4.y) + (c4.z + c4.w);
        } else {
            sqi[t] = g_sq[b*NPT + i0 + t];
            sqj[t] = g_sq[b*NPT + j0 + t];
        }
    }
    const float* XiH = g_Xhi + (size_t)(b*NPT + i0)*C;
    const float* XiL = g_Xlo + (size_t)(b*NPT + i0)*C;
    const float* XjH = g_Xhi + (size_t)(b*NPT + j0)*C;
    const float* XjL = g_Xlo + (size_t)(b*NPT + j0)*C;
    uint32_t smb = smem_u32(sm);
    constexpr int NC = C/32;
    float c[2][4][4] = {};
    #pragma unroll 1
    for (int ch = 0; ch < NC; ch++) {
        __syncthreads();
        for (int e = t; e < 4096; e += 512) {
            int arr = e >> 10, le = e & 1023, row = le >> 3, q = le & 7;
            const float* src = (arr == 0) ? XiH : (arr == 1) ? XiL : (arr == 2) ? XjH : XjL;
            uint32_t dst = smb + (uint32_t)(arr*4096 + row*32 + 4*(q ^ (row & 7)))*4u;
            cpa16(dst, src + (size_t)row*C + ch*32 + q*4);
        }
        CPA_COMMIT(); CPA_WAIT0();
        __syncthreads();
        chunk_gemm(sm, sm + 8192, c, rb, cb, g, tq);
    }
    __syncthreads();
    float* stage = sm;
    #pragma unroll
    for (int mt = 0; mt < 2; mt++) {
        int r0 = rb + mt*16 + g;
        float si0 = sqi[r0], si1 = sqi[r0 + 8];
        #pragma unroll
        for (int nt = 0; nt < 4; nt++) {
            int cl = cb + nt*8 + 2*tq;
            float sj0 = sqj[cl], sj1 = sqj[cl + 1];
            stage[r0*132 + cl]     = si0 + sj0 - 2.f*c[mt][nt][0];
            stage[r0*132 + cl + 1] = si0 + sj1 - 2.f*c[mt][nt][1];
            stage[(r0+8)*132 + cl]     = si1 + sj0 - 2.f*c[mt][nt][2];
            stage[(r0+8)*132 + cl + 1] = si1 + sj1 - 2.f*c[mt][nt][3];
        }
    }
    __syncthreads();
    float* Db = g_D + (size_t)b*NPT*NPT;
    for (int e = t; e < 4096; e += 512) {
        int r = e >> 5, q = e & 31;
        float4 v = *(const float4*)(stage + r*132 + q*4);
        *(float4*)(Db + (size_t)(i0 + r)*NPT + j0 + q*4) = v;
    }
    if (bi != bj) {
        __syncthreads();
        #pragma unroll
        for (int mt = 0; mt < 2; mt++) {
            int r0 = rb + mt*16 + g;
            float si0 = sqi[r0], si1 = sqi[r0 + 8];
            #pragma unroll
            for (int nt = 0; nt < 4; nt++) {
                int cl = cb + nt*8 + 2*tq;
                float sj0 = sqj[cl], sj1 = sqj[cl + 1];
                stage[cl*132 + r0]     = si0 + sj0 - 2.f*c[mt][nt][0];
                stage[(cl+1)*132 + r0] = si0 + sj1 - 2.f*c[mt][nt][1];
                stage[cl*132 + r0 + 8]     = si1 + sj0 - 2.f*c[mt][nt][2];
                stage[(cl+1)*132 + r0 + 8] = si1 + sj1 - 2.f*c[mt][nt][3];
            }
        }
        __syncthreads();
        for (int e = t; e < 4096; e += 512) {
            int r = e >> 5, q = e & 31;
            float4 v = *(const float4*)(stage + r*132 + q*4);
            *(float4*)(Db + (size_t)(j0 + r)*NPT + i0 + q*4) = v;
        }
    }
}

// ======== top-16: register-resident candidates ========
__global__ __launch_bounds__(256) void topk_kernel() {
    __shared__ float rbest[8]; __shared__ int ribest[8]; __shared__ int winner;
    int row = blockIdx.x, t = threadIdx.x;
    const float* Dr = g_D + (size_t)row * NPT;
    float v[8];
    #pragma unroll
    for (int u = 0; u < 8; u++) v[u] = Dr[t + u*256];
    #pragma unroll 1
    for (int it = 0; it < KNB; it++) {
        float best = v[0]; int bu = 0;
        #pragma unroll
        for (int u = 1; u < 8; u++) if (v[u] < best) { best = v[u]; bu = u; }
        int bi = t + bu*256;
        #pragma unroll
        for (int o = 16; o; o >>= 1) {
            float ov = __shfl_down_sync(0xffffffffu, best, o);
            int   oi = __shfl_down_sync(0xffffffffu, bi, o);
            if (ov < best || (ov == best && oi < bi)) { best = ov; bi = oi; }
        }
        if ((t & 31) == 0) { rbest[t>>5] = best; ribest[t>>5] = bi; }
        __syncthreads();
        if (t == 0) {
            #pragma unroll
            for (int w = 1; w < 8; w++)
                if (rbest[w] < best || (rbest[w] == best && ribest[w] < bi)) { best = rbest[w]; bi = ribest[w]; }
            g_idx[row*KNB + it] = bi;
            winner = bi;
        }
        __syncthreads();
        int wbi = winner;
        if ((wbi & 255) == t) {
            int uu = wbi >> 8;
            #pragma unroll
            for (int u = 0; u < 8; u++) if (u == uu) v[u] = FLT_MAX;
        }
    }
}

// ======== block 1 edge MLP + fused sq/split for stage 2 ========
__global__ __launch_bounds__(128) void mlp1_kernel(
        const float* __restrict__ x,
        const float* __restrict__ w1, const float* __restrict__ b1,
        const float* __restrict__ w2, const float* __restrict__ b2,
        const float* __restrict__ w3, const float* __restrict__ b3) {
    __shared__ float s1[96], sb1[16], s2[1024], sb2[64], s3[2048], sb3[32];
    int t = threadIdx.x;
    if (t < 96) s1[t] = w1[t];
    if (t < 16) sb1[t] = b1[t];
    for (int e = t; e < 1024; e += 128) s2[e] = w2[e];
    if (t < 64) sb2[t] = b2[t];
    for (int e = t; e < 2048; e += 128) s3[e] = w3[e];
    if (t < 32) sb3[t] = b3[t];
    __syncthreads();
    int k = t & 15, lp = t >> 4;
    int p = blockIdx.x * 8 + lp, b = p >> 11;
    int j = g_idx[p*KNB + k];
    const float* xc = x + (size_t)p*3;
    const float* xn = x + (size_t)(b*NPT + j)*3;
    float in[6] = { xc[0], xc[1], xc[2], xn[0], xn[1], xn[2] };
    float h16[16];
    #pragma unroll
    for (int o4 = 0; o4 < 4; o4++) {
        float4 a = *(const float4*)(sb1 + o4*4);
        #pragma unroll
        for (int c = 0; c < 6; c++) {
            float4 w = *(const float4*)(s1 + c*16 + o4*4);
            float v = in[c];
            a.x += w.x*v; a.y += w.y*v; a.z += w.z*v; a.w += w.w*v;
        }
        h16[o4*4+0] = lrelu(a.x); h16[o4*4+1] = lrelu(a.y);
        h16[o4*4+2] = lrelu(a.z); h16[o4*4+3] = lrelu(a.w);
    }
    float h32[32];
    #pragma unroll
    for (int o = 0; o < 32; o++) h32[o] = sb3[o];
    #pragma unroll
    for (int oc = 0; oc < 4; oc++) {
        float t16[16];
        #pragma unroll
        for (int o4 = 0; o4 < 4; o4++) {
            float4 a = *(const float4*)(sb2 + oc*16 + o4*4);
            #pragma unroll
            for (int c = 0; c < 16; c++) {
                float4 w = *(const float4*)(s2 + c*64 + oc*16 + o4*4);
                float v = h16[c];
                a.x += w.x*v; a.y += w.y*v; a.z += w.z*v; a.w += w.w*v;
            }
            t16[o4*4+0] = lrelu(a.x); t16[o4*4+1] = lrelu(a.y);
            t16[o4*4+2] = lrelu(a.z); t16[o4*4+3] = lrelu(a.w);
        }
        #pragma unroll
        for (int cc = 0; cc < 16; cc++) {
            float v = t16[cc];
            int c = oc*16 + cc;
            #pragma unroll
            for (int o4 = 0; o4 < 8; o4++) {
                float4 w = *(const float4*)(s3 + c*32 + o4*4);
                h32[o4*4+0] += w.x*v; h32[o4*4+1] += w.y*v;
                h32[o4*4+2] += w.z*v; h32[o4*4+3] += w.w*v;
            }
        }
    }
    #pragma unroll
    for (int c = 0; c < 32; c++) {
        float v = lrelu(h32[c]);
        #pragma unroll
        for (int o = 8; o; o >>= 1) v += __shfl_xor_sync(0xffffffffu, v, o);
        h32[c] = v;
    }
    if (k == 0) {
        float* outp = g_x2 + (size_t)p*32;
        float* hip  = g_Xhi + (size_t)p*32;
        float* lop  = g_Xlo + (size_t)p*32;
        float sq = 0.f;
        #pragma unroll
        for (int c = 0; c < 32; c++) {
            float v = h32[c];
            outp[c] = v;
            sq += v*v;
            float hi = tf32r(v);
            hip[c] = hi;
            lop[c] = tf32r(v - hi);
        }
        g_sq[p] = sq;
    }
}

// ======== factored layer-1 projections ========
template<int CIN, int COUT>
__global__ __launch_bounds__(256) void proj_kernel(
        const float* __restrict__ X, const float* __restrict__ W,
        const float* __restrict__ bias) {
    constexpr int OG = COUT/4;
    constexpr int R  = 256/OG;
    __shared__ float sin[R][CIN];
    int t = threadIdx.x, p0 = blockIdx.x * R;
    for (int e = t; e < R*CIN; e += 256) sin[e/CIN][e%CIN] = X[(size_t)p0*CIN + e];
    __syncthreads();
    int og = t % OG, r = t / OG;
    float4 aa = {0,0,0,0}, bb = {0,0,0,0};
    #pragma unroll 4
    for (int c = 0; c < CIN; c++) {
        float v = sin[r][c];
        float4 wa = *(const float4*)(W + (size_t)c*COUT + og*4);
        float4 wb = *(const float4*)(W + (size_t)(CIN+c)*COUT + og*4);
        aa.x += wa.x*v; aa.y += wa.y*v; aa.z += wa.z*v; aa.w += wa.w*v;
        bb.x += wb.x*v; bb.y += wb.y*v; bb.z += wb.z*v; bb.w += wb.w*v;
    }
    float4 b4 = *(const float4*)(bias + og*4);
    aa.x += b4.x; aa.y += b4.y; aa.z += b4.z; aa.w += b4.w;
    *(float4*)(g_A  + (size_t)(p0+r)*COUT + og*4) = aa;
    *(float4*)(g_Bf + (size_t)(p0+r)*COUT + og*4) = bb;
}

// ======== block 2 layer-2 via mma.sync + fused sq/split for stage 3, 2 CTA/SM ========
#define MLP2_SM (17152*4)
__global__ __launch_bounds__(512, 2) void mlp2_mma(const float* __restrict__ b2) {
    extern __shared__ __align__(16) float sm[];
    float* Hhi = sm;
    float* b2s = sm + 16896;
    int*   rowsrc = (int*)(sm + 17024);
    int t = threadIdx.x, wid = t >> 5, lane = t & 31;
    int g = lane >> 2, tq = lane & 3;
    int rb = (wid & 3)*32, cb = (wid >> 2)*32;
    int p0 = blockIdx.x*8, b = p0 >> 11;
    uint32_t smb = smem_u32(sm);
    if (t < 128) {
        b2s[t] = b2[t];
        rowsrc[t] = b*NPT + g_idx[(p0 + (t>>4))*KNB + (t & 15)];
    }
    __syncthreads();
    float c[2][4][4] = {};
    #pragma unroll 1
    for (int ch = 0; ch < 8; ch++) {
        for (int e = t; e < 2048; e += 512) {
            int arr = e >> 10, le = e & 1023, n = le >> 3, q = le & 7;
            const float* src = arr ? g_W2Tlo : g_W2Thi;
            uint32_t dst = smb + (uint32_t)(8192 + arr*4096 + n*32 + 4*(q ^ (n & 7)))*4u;
            cpa16(dst, src + (size_t)n*256 + ch*32 + q*4);
        }
        CPA_COMMIT();
        for (int e = t; e < 4096; e += 512) {
            int row = e >> 5, kq = e & 31, ci = ch*32 + kq;
            float v = lrelu(g_A[(size_t)(p0 + (row>>4))*256 + ci] + g_Bf[(size_t)rowsrc[row]*256 + ci]);
            float hi = tf32r(v);
            int si = swidx(row, kq);
            Hhi[si] = hi;
            Hhi[4096 + si] = tf32r(v - hi);
        }
        CPA_WAIT0();
        __syncthreads();
        chunk_gemm(Hhi, sm + 8192, c, rb, cb, g, tq);
        __syncthreads();
    }
    float* stage = sm;
    #pragma unroll
    for (int mt = 0; mt < 2; mt++) {
        int r0 = rb + mt*16 + g;
        #pragma unroll
        for (int nt = 0; nt < 4; nt++) {
            int cl = cb + nt*8 + 2*tq;
            float bb0 = b2s[cl], bb1 = b2s[cl + 1];
            stage[r0*132 + cl]     = lrelu(c[mt][nt][0] + bb0);
            stage[r0*132 + cl + 1] = lrelu(c[mt][nt][1] + bb1);
            stage[(r0+8)*132 + cl]     = lrelu(c[mt][nt][2] + bb0);
            stage[(r0+8)*132 + cl + 1] = lrelu(c[mt][nt][3] + bb1);
        }
    }
    __syncthreads();
    for (int o = t; o < 1024; o += 512) {
        int pl = o >> 7, cl = o & 127;
        const float* sp = stage + (pl*16)*132 + cl;
        float s = 0.f;
        #pragma unroll
        for (int kk = 0; kk < 16; kk++) s += sp[kk*132];
        size_t gi = (size_t)(p0 + pl)*128 + cl;
        g_x3[gi] = s;
        float hi = tf32r(s);
        g_Xhi[gi] = hi;
        g_Xlo[gi] = tf32r(s - hi);
        float ss = s*s;
        #pragma unroll
        for (int sh = 16; sh; sh >>= 1) ss += __shfl_xor_sync(0xffffffffu, ss, sh);
        if ((t & 31) == 0) g_sq4[(size_t)(p0 + pl)*4 + ((t >> 5) & 3)] = ss;
    }
}

// ======== block 3 (fully factored) ========
__global__ __launch_bounds__(128) void block3_kernel() {
    __shared__ int idxs[KNB];
    int p = blockIdx.x, t = threadIdx.x, b = p >> 11;
    if (t < KNB) idxs[t] = g_idx[p*KNB + t];
    __syncthreads();
    float a = g_A[(size_t)p*128 + t];
    float acc = 0.f;
    #pragma unroll
    for (int k = 0; k < KNB; k++)
        acc += lrelu(a + g_Bf[(size_t)(b*NPT + idxs[k])*128 + t]);
    g_x4[(size_t)p*128 + t] = acc;
}

// ======== max pool + head ========
__global__ __launch_bounds__(128) void maxpool_kernel() {
    int b = blockIdx.x, seg = blockIdx.y, t = threadIdx.x;
    const float* base = g_x4 + ((size_t)b*NPT + seg*128)*128 + t;
    float m = -FLT_MAX;
    #pragma unroll 8
    for (int r = 0; r < 128; r++) m = fmaxf(m, base[(size_t)r*128]);
    g_x5p[(b*16 + seg)*128 + t] = m;
}

__global__ __launch_bounds__(128) void final12_kernel(
        const float* __restrict__ fc1w, const float* __restrict__ fc1b,
        const float* __restrict__ fc2w, const float* __restrict__ fc2b) {
    __shared__ float s5[128], s6[128];
    int b = blockIdx.x, t = threadIdx.x;
    float m = -FLT_MAX;
    #pragma unroll
    for (int s = 0; s < 16; s++) m = fmaxf(m, g_x5p[(b*16+s)*128 + t]);
    s5[t] = m;
    __syncthreads();
    float a = fc1b[t];
    #pragma unroll 8
    for (int c = 0; c < 128; c++) a += fc1w[c*128+t]*s5[c];
    s6[t] = lrelu(a);
    __syncthreads();
    a = fc2b[t];
    #pragma unroll 8
    for (int c = 0; c < 128; c++) a += fc2w[c*128+t]*s6[c];
    g_x7[b*128 + t] = lrelu(a);
}

__global__ __launch_bounds__(128) void fc3_kernel(
        const float* __restrict__ fc3w, const float* __restrict__ fc3b,
        float* __restrict__ out) {
    __shared__ float s7[128];
    int b = blockIdx.x, seg = blockIdx.y, t = threadIdx.x;
    s7[t] = g_x7[b*128 + t];
    __syncthreads();
    int o0 = seg*512;
    float acc[4];
    #pragma unroll
    for (int u = 0; u < 4; u++) acc[u] = fc3b[o0 + u*128 + t];
    #pragma unroll 4
    for (int c = 0; c < 128; c++) {
        float v = s7[c];
        const float* wr = fc3w + (size_t)c*6144 + o0 + t;
        #pragma unroll
        for (int u = 0; u < 4; u++) acc[u] += wr[u*128]*v;
    }
    float* ob = out + (size_t)b*6144 + o0;
    #pragma unroll
    for (int u = 0; u < 4; u++) ob[u*128 + t] = acc[u];
}

// ======== host ========
extern "C" void kernel_launch(void* const* d_in, const int* in_sizes, int n_in,
                              void* d_out, int out_size) {
    const float* x    = (const float*)d_in[0];
    const float* h1w1 = (const float*)d_in[1];
    const float* h1b1 = (const float*)d_in[2];
    const float* h1w2 = (const float*)d_in[3];
    const float* h1b2 = (const float*)d_in[4];
    const float* h1w3 = (const float*)d_in[5];
    const float* h1b3 = (const float*)d_in[6];
    const float* h2w1 = (const float*)d_in[7];
    const float* h2b1 = (const float*)d_in[8];
    const float* h2w2 = (const float*)d_in[9];
    const float* h2b2 = (const float*)d_in[10];
    const float* h3w1 = (const float*)d_in[11];
    const float* h3b1 = (const float*)d_in[12];
    const float* fc1w = (const float*)d_in[13];
    const float* fc1b = (const float*)d_in[14];
    const float* fc2w = (const float*)d_in[15];
    const float* fc2b = (const float*)d_in[16];
    const float* fc3w = (const float*)d_in[17];
    const float* fc3b = (const float*)d_in[18];
    float* out = (float*)d_out;

    cudaFuncSetAttribute((const void*)dist_mma<32,false>,  cudaFuncAttributeMaxDynamicSharedMemorySize, DIST_SM);
    cudaFuncSetAttribute((const void*)dist_mma<128,true>,  cudaFuncAttributeMaxDynamicSharedMemorySize, DIST_SM);
    cudaFuncSetAttribute((const void*)mlp2_mma,            cudaFuncAttributeMaxDynamicSharedMemorySize, MLP2_SM);

    void* p2; cudaGetSymbolAddress(&p2, g_x2);
    void* p3; cudaGetSymbolAddress(&p3, g_x3);
    dim3 d3grid(32, 32, BATCH);
    dim3 trigrid(136, 1, BATCH);

    // stage 1 (C=3)
    dist3_kernel<<<d3grid, 256>>>(x);
    topk_kernel<<<BN, 256>>>();
    mlp1_kernel<<<BN/8, 128>>>(x, h1w1, h1b1, h1w2, h1b2, h1w3, h1b3);

    // stage 2 (C=32)
    dist_mma<32,false><<<trigrid, 512, DIST_SM>>>();    // launch #4 <- ncu target
    topk_kernel<<<BN, 256>>>();
    proj_kernel<32, 256><<<BN/4, 256>>>((const float*)p2, h2w1, h2b1);
    prepw2_kernel<<<128, 256>>>(h2w2);
    mlp2_mma<<<BN/8, 512, MLP2_SM>>>(h2b2);

    // stage 3 (C=128)
    dist_mma<128,true><<<trigrid, 512, DIST_SM>>>();
    topk_kernel<<<BN, 256>>>();
    proj_kernel<128, 128><<<BN/8, 256>>>((const float*)p3, h3w1, h3b1);
    block3_kernel<<<BN, 128>>>();

    // head
    maxpool_kernel<<<dim3(BATCH, 16), 128>>>();
    final12_kernel<<<BATCH, 128>>>(fc1w, fc1b, fc2w, fc2b);
    fc3_kernel<<<dim3(BATCH, 12), 128>>>(fc3w, fc3b, out);
}